// round 16
// baseline (speedup 1.0000x reference)
#include <cuda_runtime.h>
#include <math.h>

#define BATCH 8
#define PRI   24564
#define NC    80        // classes 1..80 (channel slots)
#define CDIM  93
#define TK1   400
#define TK2   200
#define NDET  (NC*TK1)  // 32000
#define OGRID 19
#define NW32  13        // ceil(400/32) 32-bit words per bitmatrix row
#define SENT  0x407FFFFFu   // f2u(-1.0f)
#define BDIM  512
#define KCAP  512       // det candidate capacity / sort size
#define CCAP  1024      // class candidate list capacity
#define T0F   0.97557f  // optimistic class threshold (expected ~600 of 24564 above)
#define CNT_STRIDE 32   // pad counters to one 128B line each (L2-slice spread)
#define NHB   1024      // det histogram bins per batch
#define NSLC  8         // det compaction slices per batch

// ---------------- scratch (device globals; no allocation allowed) ----------------
__device__ float4             g_boxes[BATCH*PRI];
__device__ unsigned long long g_cand[(size_t)BATCH*NC*CCAP];  // (key<<32)|~idx per class
__device__ int                g_candCnt[BATCH*NC*CNT_STRIDE];
__device__ int                g_selIdx[BATCH*NC*TK1];
__device__ unsigned long long g_detCompact[(size_t)BATCH*NDET]; // kept det keys, unordered
__device__ int                g_detCnt[BATCH*CNT_STRIDE];
__device__ unsigned int       g_detHist[BATCH*NHB];            // per-batch score histogram
__device__ unsigned long long g_detTop[BATCH*KCAP];            // compacted top keys (unordered)
__device__ int                g_detTopCnt[BATCH*CNT_STRIDE];
__device__ int                g_detFlag[BATCH];                // 1 => raster must run fallback

// order-preserving float<->uint transform (total order, -1 < all positives)
__device__ __forceinline__ unsigned f2u(float f){
    unsigned u = __float_as_uint(f);
    return (u & 0x80000000u) ? ~u : (u | 0x80000000u);
}
__device__ __forceinline__ float u2f(unsigned u){
    return (u & 0x80000000u) ? __uint_as_float(u & 0x7FFFFFFFu) : __uint_as_float(~u);
}

// precise expf even if harness compiles with fast-math
__device__ __forceinline__ float exp_precise(float a){
#if defined(__USE_FAST_MATH__) || defined(__FAST_MATH__)
    return (float)exp((double)a);
#else
    return expf(a);
#endif
}

// monotone map key32 -> bin in [0,1023]
__device__ __forceinline__ unsigned det_bin(unsigned k32, unsigned K0, unsigned K1v){
    if (k32 >= K1v) return 1023u;
    if (k32 <  K0)  return 0u;
    return (unsigned)(((unsigned long long)(k32 - K0) << 10) / (unsigned long long)(K1v - K0));
}

// ---------------- K0: reset per-launch counters (graph-replay safe) ----------------
__global__ void k_zero(){
    int tid = threadIdx.x;
    if (tid < BATCH*NC) g_candCnt[tid*CNT_STRIDE] = 0;
    if (tid < BATCH){
        g_detCnt[tid*CNT_STRIDE]    = 0;
        g_detTopCnt[tid*CNT_STRIDE] = 0;
        g_detFlag[tid]              = 0;
    }
    for (int j = tid; j < BATCH*NHB; j += blockDim.x) g_detHist[j] = 0u;
}

// ---------------- K1: decode boxes + push optimistic candidates ----------------
#define TPRI 32
__global__ void __launch_bounds__(128) k_decode(const float* __restrict__ x){
    __shared__ __align__(16) float tile[TPRI*CDIM];
    int b   = blockIdx.y;
    int pb  = blockIdx.x * TPRI;
    int cnt = min(TPRI, PRI - pb);
    int tid = threadIdx.x, bd = blockDim.x, lane = tid & 31;
    const float* src = x + ((size_t)b*PRI + pb)*CDIM;
    int nv = (cnt*CDIM) >> 2;
    const float4* src4 = (const float4*)src;
    float4* tile4 = (float4*)tile;
    for (int i = tid; i < nv; i += bd) tile4[i] = src4[i];
    __syncthreads();
    if (tid < cnt){
        const float* r = &tile[tid*CDIM];
        float l0=r[0], l1=r[1], l2=r[2], l3=r[3];
        float q0=r[85], q1=r[86], q2=r[87], q3=r[88];
        float v0=r[89], v1=r[90], v2=r[91], v3=r[92];
        float pw  = __fsub_rn(q2,q0), ph = __fsub_rn(q3,q1);
        float pcx = __fmul_rn(0.5f, __fadd_rn(q2,q0));
        float pcy = __fmul_rn(0.5f, __fadd_rn(q3,q1));
        float cx  = __fadd_rn(__fmul_rn(__fmul_rn(l0,pw), v0), pcx);
        float cy  = __fadd_rn(__fmul_rn(__fmul_rn(l1,pw), v1), pcy);  // ref uses pw for cy too
        float w   = __fmul_rn(exp_precise(__fmul_rn(l2,v2)), pw);
        float h   = __fmul_rn(exp_precise(__fmul_rn(l3,v3)), ph);
        float4 bx;
        bx.x = fminf(fmaxf(__fsub_rn(cx, __fmul_rn(0.5f,w)), 0.f), 1.f);
        bx.y = fminf(fmaxf(__fsub_rn(cy, __fmul_rn(0.5f,h)), 0.f), 1.f);
        bx.z = fminf(fmaxf(__fadd_rn(cx, __fmul_rn(0.5f,w)), 0.f), 1.f);
        bx.w = fminf(fmaxf(__fadd_rn(cy, __fmul_rn(0.5f,h)), 0.f), 1.f);
        g_boxes[(size_t)b*PRI + pb + tid] = bx;
    }
    // candidate push: each warp round covers one class (lane == prior-in-tile).
    // UNIFORM trip count (NC*TPRI/bd = 20) so full-mask collectives are legal.
    for (int j = tid; j < NC*TPRI; j += bd){
        int c = j >> 5, pl = lane;
        float v = (pl < cnt) ? tile[pl*CDIM + 5 + c] : 0.0f;
        bool pred = (pl < cnt) && (v > T0F);
        unsigned ball = __ballot_sync(0xFFFFFFFFu, pred);
        if (ball){
            int n = __popc(ball);
            int base = 0;
            if (lane == 0) base = atomicAdd(&g_candCnt[(b*NC + c)*CNT_STRIDE], n);
            base = __shfl_sync(0xFFFFFFFFu, base, 0);
            int pos = base + __popc(ball & ((1u << lane) - 1u));
            if (pred && pos < CCAP){
                unsigned idx = (unsigned)(pb + pl);
                g_cand[((size_t)(b*NC + c))*CCAP + pos] =
                    ((unsigned long long)f2u(v) << 32) | (~idx);
            }
        }
    }
}

// ---------------- bitonic sort (descending) over keys[0..M), M power of 2 ----------------
__device__ void bitonic_desc(unsigned long long* keys, int M){
    const int tid = threadIdx.x, bd = blockDim.x;
    for (int size = 2; size <= M; size <<= 1){
        for (int stride = size >> 1; stride > 0; stride >>= 1){
            __syncthreads();
            for (int i = tid; i < M; i += bd){
                int j = i ^ stride;
                if (j > i){
                    unsigned long long a = keys[i], b = keys[j];
                    bool up = ((i & size) == 0);
                    if (up ? (a < b) : (a > b)){ keys[i] = b; keys[j] = a; }
                }
            }
        }
    }
    __syncthreads();
}

// ---------------- exact fallback: ladder top-K reading keys straight from x --------
__device__ void topk_fallback_x(const float* __restrict__ x, int b, int c, int K,
                                unsigned long long* keys)
{
    __shared__ int s_c, s_cnt, s_eqbase;
    __shared__ int warpTot[16];
    const int tid = threadIdx.x, bd = BDIM;
    const int wid = tid >> 5, lane = tid & 31;
    const int N = PRI;
    const int target = (K + KCAP) / 2;

    auto key_at = [&](int i) -> unsigned {
        float v = x[((size_t)b*PRI + i)*CDIM + 5 + c];
        return (v > 0.01f) ? f2u(v) : SENT;
    };

    for (int i = tid; i < CCAP; i += bd) keys[i] = 0ULL;
    if (tid == 0){ s_cnt = 0; s_eqbase = 0; }

    unsigned lo = 0u, hi = 0xFFFFFFFFu;
    int clo = N, chi = 0;
    unsigned Tb = 0u;
    bool found = false;
    for (int iter = 0; iter < 140 && !found && (hi - lo) > 1u; iter++){
        unsigned T;
        if (iter == 0)      T = 0x80000000u;
        else if (iter == 1) T = 0xBF800000u;
        else if ((iter == 2) || (iter & 1)){
            double dc = (double)clo - (double)chi;
            if (dc > 0.5){
                double frac = ((double)clo - (double)target) / dc;
                if (frac < 0.0) frac = 0.0;
                if (frac > 1.0) frac = 1.0;
                T = lo + (unsigned)((double)(hi - lo) * frac);
            } else T = lo + ((hi - lo) >> 1);
        } else T = lo + ((hi - lo) >> 1);
        if (T <= lo) T = lo + 1u;
        if (T >= hi) T = hi - 1u;

        if (tid == 0) s_c = 0;
        __syncthreads();
        int cnt = 0;
        for (int i = tid; i < N; i += bd) cnt += (key_at(i) >= T) ? 1 : 0;
        #pragma unroll
        for (int o = 16; o; o >>= 1) cnt += __shfl_down_sync(0xFFFFFFFFu, cnt, o);
        if (lane == 0 && cnt) atomicAdd(&s_c, cnt);
        __syncthreads();
        int cc = s_c;
        __syncthreads();

        if (cc >= K && cc <= KCAP){ Tb = T; found = true; }
        else if (cc > KCAP){ lo = T; clo = cc; }
        else               { hi = T; chi = cc; }
    }

    if (found){
        const unsigned Tv = Tb;
        for (int base = 0; base < N; base += bd){
            int i = base + tid;
            bool inb = (i < N);
            unsigned vv = inb ? key_at(i) : 0u;
            bool pred = inb && (vv >= Tv);
            unsigned ball = __ballot_sync(0xFFFFFFFFu, pred);
            int cntw = __popc(ball);
            int wbase = 0;
            if (lane == 0 && cntw) wbase = atomicAdd(&s_cnt, cntw);
            wbase = __shfl_sync(0xFFFFFFFFu, wbase, 0);
            if (pred){
                int off = __popc(ball & ((1u << lane) - 1u));
                keys[wbase + off] = ((unsigned long long)vv << 32) | (unsigned)(~(unsigned)i);
            }
        }
        __syncthreads();
        bitonic_desc(keys, KCAP);
    } else {
        const unsigned T = lo;
        for (int base = 0; base < N; base += bd){
            int i = base + tid;
            bool inb = (i < N);
            unsigned vv = inb ? key_at(i) : 0u;
            bool pred = inb && (vv > T);
            unsigned ball = __ballot_sync(0xFFFFFFFFu, pred);
            int cntw = __popc(ball);
            int wbase = 0;
            if (lane == 0 && cntw) wbase = atomicAdd(&s_cnt, cntw);
            wbase = __shfl_sync(0xFFFFFFFFu, wbase, 0);
            if (pred){
                int off = __popc(ball & ((1u << lane) - 1u));
                if (wbase + off < KCAP)
                    keys[wbase + off] = ((unsigned long long)vv << 32) | (unsigned)(~(unsigned)i);
            }
        }
        __syncthreads();
        const int cntAbove = min(s_cnt, KCAP);
        const int need = K - cntAbove;
        for (int base = 0; base < N && s_eqbase < need; base += bd){
            int i = base + tid;
            bool eq = (i < N) && (key_at(i) == T);
            unsigned ball = __ballot_sync(0xFFFFFFFFu, eq);
            int wpre = __popc(ball & ((1u << lane) - 1u));
            if (lane == 0) warpTot[wid] = __popc(ball);
            __syncthreads();
            int pre = 0;
            for (int w = 0; w < wid; w++) pre += warpTot[w];
            int rank = s_eqbase + pre + wpre;
            if (eq && rank < need && cntAbove + rank < KCAP)
                keys[cntAbove + rank] = ((unsigned long long)T << 32) | (unsigned)(~(unsigned)i);
            __syncthreads();
            if (tid == 0){ int tot = 0; for (int w = 0; w < 16; w++) tot += warpTot[w]; s_eqbase += tot; }
            __syncthreads();
        }
        __syncthreads();
        bitonic_desc(keys, KCAP);
    }
}

// IoU > 0.45 test, exact on the boundary band
__device__ __forceinline__ bool iou_gt(const float4& a, float aa, const float4& d, float dd){
    float ix1 = fmaxf(a.x, d.x), iy1 = fmaxf(a.y, d.y);
    float ix2 = fminf(a.z, d.z), iy2 = fminf(a.w, d.w);
    float iw = fmaxf(__fsub_rn(ix2, ix1), 0.0f);
    float ih = fmaxf(__fsub_rn(iy2, iy1), 0.0f);
    float inter = __fmul_rn(iw, ih);
    if (inter <= 0.0f) return false;
    float uni = __fsub_rn(__fadd_rn(aa, dd), inter);
    if (uni <= 0.0f) return false;
    if (inter > 0.46f*uni) return true;
    if (inter < 0.44f*uni) return false;
    return __fdiv_rn(inter, uni) > 0.45f;
}

// ---------------- K2: fused per-(b,c) candidate sort + greedy NMS + det push --------
#define SMEMA_BYTES 20864   // max(keys 1024*8 = 8192, smat 400*13*4 = 20800)
__global__ void __launch_bounds__(BDIM, 3) k_class(const float* __restrict__ x){
    __shared__ __align__(16) unsigned char smemA[SMEMA_BYTES];
    __shared__ float4 sbox[TK1];
    __shared__ float  sarea[TK1];
    __shared__ float  sS[TK1];
    __shared__ unsigned skept[NW32];
    unsigned long long* keys = (unsigned long long*)smemA;
    unsigned*           smat = (unsigned*)smemA;   // overwrites keys after consumption

    int bc = blockIdx.x, b = bc / NC, c = bc % NC;
    int tid = threadIdx.x, bd = blockDim.x, wid = tid >> 5, lane = tid & 31;

    int cnt = g_candCnt[bc*CNT_STRIDE];
    if (cnt >= TK1 && cnt <= CCAP){
        // happy path: exact top-400 guaranteed inside candidate list
        const unsigned long long* src = &g_cand[(size_t)bc*CCAP];
        for (int i = tid; i < CCAP; i += bd) keys[i] = (i < cnt) ? src[i] : 0ULL;
        __syncthreads();
        bitonic_desc(keys, CCAP);
    } else {
        topk_fallback_x(x, b, c, TK1, keys);   // exact, rare
    }

    for (int r = tid; r < TK1; r += bd){
        unsigned long long kk = keys[r];
        int idx  = (int)(~(unsigned)(kk & 0xFFFFFFFFu));
        float sc = u2f((unsigned)(kk >> 32));
        float4 bx = g_boxes[(size_t)b*PRI + idx];
        sbox[r] = bx; sS[r] = sc;
        sarea[r] = __fmul_rn(__fsub_rn(bx.z,bx.x), __fsub_rn(bx.w,bx.y));
        g_selIdx[bc*TK1 + r] = idx;
    }
    __syncthreads();   // keys fully consumed; smat may overwrite

    // transposed, task-balanced suppression bitmatrix over 16 warps.
    for (int t = wid; t < 91; t += 16){
        int wdx = 0, rem = t;
        while (rem >= NW32 - wdx){ rem -= NW32 - wdx; wdx++; }
        int ichunk = wdx + rem;
        int jb = wdx << 5, ib = ichunk << 5;
        int jj = jb + lane;
        int jjc = min(jj, TK1 - 1);
        float4 jb4 = sbox[jjc]; float ja = sarea[jjc];
        int imax = min(32, TK1 - ib);
        for (int ii = 0; ii < imax; ii++){
            int i = ib + ii;
            float4 a = sbox[i]; float aa = sarea[i];   // broadcast
            bool gt = (jj < i) && iou_gt(a, aa, jb4, ja);
            unsigned m = __ballot_sync(0xFFFFFFFFu, gt);
            if (lane == ii) smat[i*NW32 + wdx] = m;
        }
    }
    __syncthreads();

    // sequential greedy scan; scan-warp varies per block to spread across SMSPs
    int swid = blockIdx.x & 15;
    if (wid == swid){
        unsigned kept32 = 0;
        unsigned row = (lane < NW32) ? smat[lane] : 0u;
        float sc = sS[0];
        for (int i = 0; i < TK1; i++){
            unsigned nrow = 0u; float nsc = 0.f;
            if (i + 1 < TK1){
                if (lane < NW32) nrow = smat[(i+1)*NW32 + lane];
                nsc = sS[i+1];
            }
            bool any = __any_sync(0xFFFFFFFFu, (row & kept32) != 0u);
            if (sc > 0.01f && !any && lane == (i >> 5)) kept32 |= 1u << (i & 31);
            row = nrow; sc = nsc;
        }
        if (lane < NW32) skept[lane] = kept32;
    }
    __syncthreads();

    // push kept dets (unordered) + histogram increment.
    // bd = 512 >= TK1: single UNIFORM round so full-mask collectives are legal.
    const unsigned K0 = f2u(T0F), K1v = f2u(1.0f);
    for (int base = 0; base < TK1; base += bd){
        int r = base + tid;
        bool inb = (r < TK1);
        bool kp = false; float sc = -1.0f;
        if (inb){
            kp = (skept[r >> 5] >> (r & 31)) & 1u;
            sc = sS[r];
        }
        unsigned ball = __ballot_sync(0xFFFFFFFFu, kp);
        int n = __popc(ball);
        int wbase = 0;
        if (lane == 0 && n) wbase = atomicAdd(&g_detCnt[b*CNT_STRIDE], n);
        wbase = __shfl_sync(0xFFFFFFFFu, wbase, 0);
        if (kp){
            int off = __popc(ball & ((1u << lane) - 1u));
            unsigned flat = (unsigned)(c*TK1 + r);
            unsigned k32 = f2u(sc);
            g_detCompact[(size_t)b*NDET + wbase + off] =
                ((unsigned long long)k32 << 32) | (~flat);
            atomicAdd(&g_detHist[b*NHB + det_bin(k32, K0, K1v)], 1u);
        }
    }
}

// ---------------- K3a: 64-block det threshold + slice compaction ----------------
__global__ void __launch_bounds__(512) k_det_compact(){
    __shared__ unsigned long long s_TB;
    __shared__ int s_ok;
    __shared__ unsigned wtot[16];
    int blk = blockIdx.x;
    int b = blk >> 3, s = blk & (NSLC-1);
    int tid = threadIdx.x, bd = blockDim.x;
    int wid = tid >> 5, lane = tid & 31;

    int N = min(g_detCnt[b*CNT_STRIDE], NDET);
    int s0 = (N * s) / NSLC;
    int s1 = (N * (s + 1)) / NSLC;
    const unsigned long long* g = &g_detCompact[(size_t)b*NDET];

    if (tid == 0) s_ok = 0;
    __syncthreads();

    unsigned long long Tb = 0ULL;
    bool useTb = false;
    if (N > KCAP){
        // threshold from precomputed histogram; 2 bins per thread
        const unsigned K0 = f2u(T0F), K1v = f2u(1.0f);
        int b0 = tid*2;
        unsigned h0 = g_detHist[b*NHB + b0];
        unsigned h1 = g_detHist[b*NHB + b0 + 1];
        unsigned sown = h0 + h1;
        unsigned ssuf = sown;
        #pragma unroll
        for (int o = 1; o < 32; o <<= 1){
            unsigned xv = __shfl_down_sync(0xFFFFFFFFu, ssuf, o);
            if (lane + o < 32) ssuf += xv;
        }
        if (lane == 0) wtot[wid] = ssuf;
        __syncthreads();
        unsigned wab = 0;
        for (int w = wid + 1; w < 16; w++) wab += wtot[w];
        unsigned St = ssuf + wab;          // suffix incl both own bins
        unsigned above = St - sown;        // suffix of bins > b0+1
        // check crossing within own two bins (high bin first)
        int crossBin = -1; unsigned crossSuffix = 0;
        unsigned run = above;
        if ((int)run < TK2 && (int)(run + h1) >= TK2){ crossBin = b0 + 1; crossSuffix = run + h1; }
        run += h1;
        if (crossBin < 0 && (int)run < TK2 && (int)(run + h0) >= TK2){ crossBin = b0; crossSuffix = run + h0; }
        if (crossBin >= 0 && crossSuffix <= KCAP){
            unsigned tb32 = (crossBin == 0) ? 0u
                : K0 + (unsigned)((((unsigned long long)crossBin * (K1v - K0)) + 1023ULL) >> 10);
            s_TB = (crossBin == 0) ? 0ULL : ((unsigned long long)tb32 << 32);
            s_ok = 1;
        }
        __syncthreads();
        if (s_ok){ Tb = s_TB; useTb = true; }
        else {
            if (tid == 0 && s == 0) g_detFlag[b] = 1;   // raster runs full fallback
            return;
        }
    }
    __syncthreads();

    // compact slice keys (>= Tb, or all if N <= KCAP) into g_detTop[b]
    int len = s1 - s0;
    for (int base = 0; base < len; base += bd){
        int i = base + tid;
        bool inb = (i < len);
        unsigned long long v = inb ? g[s0 + i] : 0ULL;
        bool pred = inb && (!useTb || v >= Tb);
        unsigned ball = __ballot_sync(0xFFFFFFFFu, pred);
        int n = __popc(ball);
        int wbase = 0;
        if (lane == 0 && n) wbase = atomicAdd(&g_detTopCnt[b*CNT_STRIDE], n);
        wbase = __shfl_sync(0xFFFFFFFFu, wbase, 0);
        if (pred){
            int off = __popc(ball & ((1u << lane) - 1u));
            if (wbase + off < KCAP) g_detTop[b*KCAP + wbase + off] = v;
        }
    }
}

// ---------------- K3b: per-batch sort of <=512 keys + rasterize ----------------
__global__ void __launch_bounds__(1024) k_det_raster(float* __restrict__ out){
    __shared__ unsigned hist[4096];        // fallback range-refine scratch
    __shared__ __align__(16) unsigned long long keys[KCAP];
    __shared__ unsigned long long wmn[32], wmx[32];
    __shared__ unsigned long long s_lo, s_hi, s_T;
    __shared__ int s_above, s_done, s_cnt;
    __shared__ unsigned wtot[32];
    __shared__ float sS2[TK2];
    __shared__ int   sCh[TK2];
    __shared__ int4  sCo[TK2];
    __shared__ unsigned char sV[TK2];
    int b = blockIdx.x, tid = threadIdx.x, bd = blockDim.x;
    int wid = tid >> 5, lane = tid & 31;

    if (tid == 0){ s_cnt = 0; s_done = 0; s_above = 0; }
    __syncthreads();

    if (!g_detFlag[b]){
        // fast path: <=512 pre-compacted keys
        int cnt = min(g_detTopCnt[b*CNT_STRIDE], KCAP);
        for (int i = tid; i < KCAP; i += bd)
            keys[i] = (i < cnt) ? g_detTop[b*KCAP + i] : 0ULL;
        __syncthreads();
        bitonic_desc(keys, KCAP);
    } else {
        // fallback: r14 deterministic range-refining histogram select on full list
        const unsigned long long* g = &g_detCompact[(size_t)b*NDET];
        int N = min(g_detCnt[b*CNT_STRIDE], NDET);
        for (int i = tid; i < KCAP; i += bd) keys[i] = 0ULL;
        __syncthreads();
        unsigned long long mn = 0xFFFFFFFFFFFFFFFFULL, mx = 0ULL;
        for (int i = tid; i < N; i += bd){
            unsigned long long v = g[i];
            if (v < mn) mn = v;
            if (v > mx) mx = v;
        }
        #pragma unroll
        for (int o = 16; o; o >>= 1){
            unsigned long long a = __shfl_down_sync(0xFFFFFFFFu, mn, o);
            unsigned long long z = __shfl_down_sync(0xFFFFFFFFu, mx, o);
            if (a < mn) mn = a;
            if (z > mx) mx = z;
        }
        if (lane == 0){ wmn[wid] = mn; wmx[wid] = mx; }
        __syncthreads();
        if (tid == 0){
            unsigned long long m1 = wmn[0], m2 = wmx[0];
            for (int w = 1; w < 32; w++){
                if (wmn[w] < m1) m1 = wmn[w];
                if (wmx[w] > m2) m2 = wmx[w];
            }
            s_lo = m1; s_hi = m2;
        }
        __syncthreads();
        for (int pass = 0; pass < 10 && !s_done; pass++){
            unsigned long long lo = s_lo, hi = s_hi;
            int above = s_above;
            unsigned long long range = hi - lo;
            int bits = 64 - __clzll(range | 1ULL);
            int shift = (bits > 12) ? (bits - 12) : 0;
            int nb = (int)((range >> shift) + 1ULL);
            for (int i = tid; i < nb; i += bd) hist[i] = 0u;
            __syncthreads();
            for (int i = tid; i < N; i += bd){
                unsigned long long v = g[i];
                if (v >= lo && v <= hi)
                    atomicAdd(&hist[(unsigned)((v - lo) >> shift)], 1u);
            }
            __syncthreads();
            int b0 = tid * 4;
            int bhi2 = min(b0 + 4, nb);
            unsigned sown = 0;
            for (int bb = b0; bb < bhi2; bb++) sown += hist[bb];
            unsigned ssuf2 = sown;
            #pragma unroll
            for (int o = 1; o < 32; o <<= 1){
                unsigned xv = __shfl_down_sync(0xFFFFFFFFu, ssuf2, o);
                if (lane + o < 32) ssuf2 += xv;
            }
            if (lane == 0) wtot[wid] = ssuf2;
            __syncthreads();
            unsigned wab2 = 0;
            for (int w = wid + 1; w < 32; w++) wab2 += wtot[w];
            unsigned St2 = ssuf2 + wab2;
            unsigned aboveT = St2 - sown;
            __syncthreads();
            if (b0 < nb && (int)(above + St2) >= TK2 && (int)(above + aboveT) < TK2){
                int running = above + (int)aboveT;
                for (int bb = bhi2 - 1; bb >= b0; bb--){
                    int cb = (int)hist[bb];
                    if (running < TK2 && running + cb >= TK2){
                        unsigned long long Tc = lo + ((unsigned long long)bb << shift);
                        if (running + cb <= KCAP){ s_T = Tc; s_done = 1; }
                        else {
                            s_lo = Tc;
                            unsigned long long nhix = lo + (((unsigned long long)bb + 1ULL) << shift) - 1ULL;
                            s_hi = (nhix < hi) ? nhix : hi;
                            s_above = running;
                        }
                        break;
                    }
                    running += cb;
                }
            }
            __syncthreads();
        }
        unsigned long long Tb = s_done ? s_T : s_lo;
        for (int base = 0; base < N; base += bd){
            int i = base + tid;
            bool pred = (i < N) && (g[i] >= Tb);
            unsigned long long v = pred ? g[i] : 0ULL;
            unsigned ball = __ballot_sync(0xFFFFFFFFu, pred);
            int n = __popc(ball);
            int wbase = 0;
            if (lane == 0 && n) wbase = atomicAdd(&s_cnt, n);
            wbase = __shfl_sync(0xFFFFFFFFu, wbase, 0);
            if (pred){
                int off = __popc(ball & ((1u << lane) - 1u));
                if (wbase + off < KCAP) keys[wbase + off] = v;
            }
        }
        __syncthreads();
        bitonic_desc(keys, KCAP);
    }

    for (int k = tid; k < TK2; k += bd){
        unsigned long long kk = keys[k];
        int fi   = (int)(~(unsigned)(kk & 0xFFFFFFFFu));
        float s  = u2f((unsigned)(kk >> 32));
        int c = fi / TK1, r = fi % TK1;
        bool valid = (kk != 0ULL) && (s >= 0.6f);
        int idx = valid ? g_selIdx[(b*NC + c)*TK1 + r] : 0;
        float4 bx = g_boxes[(size_t)b*PRI + idx];
        int4 co;
        co.x = (int)rintf(__fmul_rn(bx.x, (float)OGRID));
        co.y = (int)rintf(__fmul_rn(bx.y, (float)OGRID));
        co.z = (int)rintf(__fmul_rn(bx.z, (float)OGRID));
        co.w = (int)rintf(__fmul_rn(bx.w, (float)OGRID));
        sS2[k] = s; sCh[k] = valid ? c : 0; sCo[k] = co; sV[k] = valid ? 1 : 0;
    }
    __syncthreads();

    for (int cell = tid; cell < OGRID*OGRID; cell += bd){
        int y = cell / OGRID, xp = cell % OGRID;
        float* o = out + ((size_t)b*OGRID*OGRID + cell) * 81;
        for (int ch = 0; ch < 81; ch++) o[ch] = 0.0f;
        for (int k = 0; k < TK2; k++){
            if (sV[k]){
                int4 co = sCo[k];
                if (y >= co.y && y < co.w && xp >= co.x && xp < co.z)
                    o[sCh[k]] = sS2[k];     // ascending k: last writer == max k
            }
        }
    }
}

// ---------------- launch ----------------
extern "C" void kernel_launch(void* const* d_in, const int* in_sizes, int n_in,
                              void* d_out, int out_size){
    const float* x = (const float*)d_in[0];
    float* out = (float*)d_out;
    k_zero<<<1, 1024>>>();
    dim3 g1((PRI + TPRI - 1) / TPRI, BATCH);
    k_decode<<<g1, 128>>>(x);
    k_class<<<BATCH*NC, BDIM>>>(x);
    k_det_compact<<<BATCH*NSLC, 512>>>();
    k_det_raster<<<BATCH, 1024>>>(out);
}

// round 17
// speedup vs baseline: 1.0812x; 1.0812x over previous
#include <cuda_runtime.h>
#include <math.h>

#define BATCH 8
#define PRI   24564
#define NC    80        // classes 1..80 (channel slots)
#define CDIM  93
#define TK1   400
#define TK2   200
#define NDET  (NC*TK1)  // 32000
#define OGRID 19
#define NW32  13        // ceil(400/32) 32-bit words per bitmatrix row
#define SENT  0x407FFFFFu   // f2u(-1.0f)
#define BDIM  512
#define KCAP  512       // det candidate capacity / sort size
#define CCAP  1024      // class candidate list capacity
#define T0F   0.97557f  // optimistic class threshold (expected ~600 of 24564 above)
#define CNT_STRIDE 32   // pad counters to one 128B line each (L2-slice spread)
#define NHB   1024      // det histogram bins per batch
#define NSLC  8         // det compaction slices per batch

// ---------------- scratch (device globals; no allocation allowed) ----------------
__device__ float4             g_boxes[BATCH*PRI];
__device__ unsigned long long g_cand[(size_t)BATCH*NC*CCAP];  // (key<<32)|~idx per class
__device__ int                g_candCnt[BATCH*NC*CNT_STRIDE];
__device__ int                g_selIdx[BATCH*NC*TK1];
__device__ unsigned long long g_detCompact[(size_t)BATCH*NDET]; // kept det keys, unordered
__device__ int                g_detCnt[BATCH*CNT_STRIDE];
__device__ unsigned int       g_detHist[BATCH*NHB];            // per-batch score histogram
__device__ unsigned long long g_detTop[BATCH*KCAP];            // compacted top keys (unordered)
__device__ int                g_detTopCnt[BATCH*CNT_STRIDE];
__device__ int                g_detFlag[BATCH];                // 1 => raster must run fallback

// order-preserving float<->uint transform (total order, -1 < all positives)
__device__ __forceinline__ unsigned f2u(float f){
    unsigned u = __float_as_uint(f);
    return (u & 0x80000000u) ? ~u : (u | 0x80000000u);
}
__device__ __forceinline__ float u2f(unsigned u){
    return (u & 0x80000000u) ? __uint_as_float(u & 0x7FFFFFFFu) : __uint_as_float(~u);
}

// precise expf even if harness compiles with fast-math
__device__ __forceinline__ float exp_precise(float a){
#if defined(__USE_FAST_MATH__) || defined(__FAST_MATH__)
    return (float)exp((double)a);
#else
    return expf(a);
#endif
}

// monotone map key32 -> bin in [0,1023]
__device__ __forceinline__ unsigned det_bin(unsigned k32, unsigned K0, unsigned K1v){
    if (k32 >= K1v) return 1023u;
    if (k32 <  K0)  return 0u;
    return (unsigned)(((unsigned long long)(k32 - K0) << 10) / (unsigned long long)(K1v - K0));
}
// monotone map key32 -> bin in [0,511] (class prune)
__device__ __forceinline__ unsigned cls_bin(unsigned k32, unsigned K0, unsigned K1v){
    if (k32 >= K1v) return 511u;
    if (k32 <  K0)  return 0u;
    return (unsigned)(((unsigned long long)(k32 - K0) << 9) / (unsigned long long)(K1v - K0));
}

// ---------------- K0: reset per-launch counters (graph-replay safe) ----------------
__global__ void k_zero(){
    int tid = threadIdx.x;
    if (tid < BATCH*NC) g_candCnt[tid*CNT_STRIDE] = 0;
    if (tid < BATCH){
        g_detCnt[tid*CNT_STRIDE]    = 0;
        g_detTopCnt[tid*CNT_STRIDE] = 0;
        g_detFlag[tid]              = 0;
    }
    for (int j = tid; j < BATCH*NHB; j += blockDim.x) g_detHist[j] = 0u;
}

// ---------------- no-op (ncu capture-slot steering) ----------------
__global__ void k_nop(){}

// ---------------- K1: decode boxes + push optimistic candidates ----------------
#define TPRI 32
__global__ void __launch_bounds__(128) k_decode(const float* __restrict__ x){
    __shared__ __align__(16) float tile[TPRI*CDIM];
    int b   = blockIdx.y;
    int pb  = blockIdx.x * TPRI;
    int cnt = min(TPRI, PRI - pb);
    int tid = threadIdx.x, bd = blockDim.x, lane = tid & 31;
    const float* src = x + ((size_t)b*PRI + pb)*CDIM;
    int nv = (cnt*CDIM) >> 2;
    const float4* src4 = (const float4*)src;
    float4* tile4 = (float4*)tile;
    for (int i = tid; i < nv; i += bd) tile4[i] = src4[i];
    __syncthreads();
    if (tid < cnt){
        const float* r = &tile[tid*CDIM];
        float l0=r[0], l1=r[1], l2=r[2], l3=r[3];
        float q0=r[85], q1=r[86], q2=r[87], q3=r[88];
        float v0=r[89], v1=r[90], v2=r[91], v3=r[92];
        float pw  = __fsub_rn(q2,q0), ph = __fsub_rn(q3,q1);
        float pcx = __fmul_rn(0.5f, __fadd_rn(q2,q0));
        float pcy = __fmul_rn(0.5f, __fadd_rn(q3,q1));
        float cx  = __fadd_rn(__fmul_rn(__fmul_rn(l0,pw), v0), pcx);
        float cy  = __fadd_rn(__fmul_rn(__fmul_rn(l1,pw), v1), pcy);  // ref uses pw for cy too
        float w   = __fmul_rn(exp_precise(__fmul_rn(l2,v2)), pw);
        float h   = __fmul_rn(exp_precise(__fmul_rn(l3,v3)), ph);
        float4 bx;
        bx.x = fminf(fmaxf(__fsub_rn(cx, __fmul_rn(0.5f,w)), 0.f), 1.f);
        bx.y = fminf(fmaxf(__fsub_rn(cy, __fmul_rn(0.5f,h)), 0.f), 1.f);
        bx.z = fminf(fmaxf(__fadd_rn(cx, __fmul_rn(0.5f,w)), 0.f), 1.f);
        bx.w = fminf(fmaxf(__fadd_rn(cy, __fmul_rn(0.5f,h)), 0.f), 1.f);
        g_boxes[(size_t)b*PRI + pb + tid] = bx;
    }
    // candidate push: each warp round covers one class (lane == prior-in-tile).
    // UNIFORM trip count (NC*TPRI/bd = 20) so full-mask collectives are legal.
    for (int j = tid; j < NC*TPRI; j += bd){
        int c = j >> 5, pl = lane;
        float v = (pl < cnt) ? tile[pl*CDIM + 5 + c] : 0.0f;
        bool pred = (pl < cnt) && (v > T0F);
        unsigned ball = __ballot_sync(0xFFFFFFFFu, pred);
        if (ball){
            int n = __popc(ball);
            int base = 0;
            if (lane == 0) base = atomicAdd(&g_candCnt[(b*NC + c)*CNT_STRIDE], n);
            base = __shfl_sync(0xFFFFFFFFu, base, 0);
            int pos = base + __popc(ball & ((1u << lane) - 1u));
            if (pred && pos < CCAP){
                unsigned idx = (unsigned)(pb + pl);
                g_cand[((size_t)(b*NC + c))*CCAP + pos] =
                    ((unsigned long long)f2u(v) << 32) | (~idx);
            }
        }
    }
}

// ---------------- bitonic sort (descending) over keys[0..M), M power of 2 ----------------
__device__ void bitonic_desc(unsigned long long* keys, int M){
    const int tid = threadIdx.x, bd = blockDim.x;
    for (int size = 2; size <= M; size <<= 1){
        for (int stride = size >> 1; stride > 0; stride >>= 1){
            __syncthreads();
            for (int i = tid; i < M; i += bd){
                int j = i ^ stride;
                if (j > i){
                    unsigned long long a = keys[i], b = keys[j];
                    bool up = ((i & size) == 0);
                    if (up ? (a < b) : (a > b)){ keys[i] = b; keys[j] = a; }
                }
            }
        }
    }
    __syncthreads();
}

// ---------------- exact fallback: ladder top-K reading keys straight from x --------
__device__ void topk_fallback_x(const float* __restrict__ x, int b, int c, int K,
                                unsigned long long* keys)
{
    __shared__ int s_c, s_cnt, s_eqbase;
    __shared__ int warpTot[16];
    const int tid = threadIdx.x, bd = BDIM;
    const int wid = tid >> 5, lane = tid & 31;
    const int N = PRI;
    const int target = (K + KCAP) / 2;

    auto key_at = [&](int i) -> unsigned {
        float v = x[((size_t)b*PRI + i)*CDIM + 5 + c];
        return (v > 0.01f) ? f2u(v) : SENT;
    };

    for (int i = tid; i < CCAP; i += bd) keys[i] = 0ULL;
    if (tid == 0){ s_cnt = 0; s_eqbase = 0; }

    unsigned lo = 0u, hi = 0xFFFFFFFFu;
    int clo = N, chi = 0;
    unsigned Tb = 0u;
    bool found = false;
    for (int iter = 0; iter < 140 && !found && (hi - lo) > 1u; iter++){
        unsigned T;
        if (iter == 0)      T = 0x80000000u;
        else if (iter == 1) T = 0xBF800000u;
        else if ((iter == 2) || (iter & 1)){
            double dc = (double)clo - (double)chi;
            if (dc > 0.5){
                double frac = ((double)clo - (double)target) / dc;
                if (frac < 0.0) frac = 0.0;
                if (frac > 1.0) frac = 1.0;
                T = lo + (unsigned)((double)(hi - lo) * frac);
            } else T = lo + ((hi - lo) >> 1);
        } else T = lo + ((hi - lo) >> 1);
        if (T <= lo) T = lo + 1u;
        if (T >= hi) T = hi - 1u;

        if (tid == 0) s_c = 0;
        __syncthreads();
        int cnt = 0;
        for (int i = tid; i < N; i += bd) cnt += (key_at(i) >= T) ? 1 : 0;
        #pragma unroll
        for (int o = 16; o; o >>= 1) cnt += __shfl_down_sync(0xFFFFFFFFu, cnt, o);
        if (lane == 0 && cnt) atomicAdd(&s_c, cnt);
        __syncthreads();
        int cc = s_c;
        __syncthreads();

        if (cc >= K && cc <= KCAP){ Tb = T; found = true; }
        else if (cc > KCAP){ lo = T; clo = cc; }
        else               { hi = T; chi = cc; }
    }

    if (found){
        const unsigned Tv = Tb;
        for (int base = 0; base < N; base += bd){
            int i = base + tid;
            bool inb = (i < N);
            unsigned vv = inb ? key_at(i) : 0u;
            bool pred = inb && (vv >= Tv);
            unsigned ball = __ballot_sync(0xFFFFFFFFu, pred);
            int cntw = __popc(ball);
            int wbase = 0;
            if (lane == 0 && cntw) wbase = atomicAdd(&s_cnt, cntw);
            wbase = __shfl_sync(0xFFFFFFFFu, wbase, 0);
            if (pred){
                int off = __popc(ball & ((1u << lane) - 1u));
                keys[wbase + off] = ((unsigned long long)vv << 32) | (unsigned)(~(unsigned)i);
            }
        }
        __syncthreads();
        bitonic_desc(keys, KCAP);
    } else {
        const unsigned T = lo;
        for (int base = 0; base < N; base += bd){
            int i = base + tid;
            bool inb = (i < N);
            unsigned vv = inb ? key_at(i) : 0u;
            bool pred = inb && (vv > T);
            unsigned ball = __ballot_sync(0xFFFFFFFFu, pred);
            int cntw = __popc(ball);
            int wbase = 0;
            if (lane == 0 && cntw) wbase = atomicAdd(&s_cnt, cntw);
            wbase = __shfl_sync(0xFFFFFFFFu, wbase, 0);
            if (pred){
                int off = __popc(ball & ((1u << lane) - 1u));
                if (wbase + off < KCAP)
                    keys[wbase + off] = ((unsigned long long)vv << 32) | (unsigned)(~(unsigned)i);
            }
        }
        __syncthreads();
        const int cntAbove = min(s_cnt, KCAP);
        const int need = K - cntAbove;
        for (int base = 0; base < N && s_eqbase < need; base += bd){
            int i = base + tid;
            bool eq = (i < N) && (key_at(i) == T);
            unsigned ball = __ballot_sync(0xFFFFFFFFu, eq);
            int wpre = __popc(ball & ((1u << lane) - 1u));
            if (lane == 0) warpTot[wid] = __popc(ball);
            __syncthreads();
            int pre = 0;
            for (int w = 0; w < wid; w++) pre += warpTot[w];
            int rank = s_eqbase + pre + wpre;
            if (eq && rank < need && cntAbove + rank < KCAP)
                keys[cntAbove + rank] = ((unsigned long long)T << 32) | (unsigned)(~(unsigned)i);
            __syncthreads();
            if (tid == 0){ int tot = 0; for (int w = 0; w < 16; w++) tot += warpTot[w]; s_eqbase += tot; }
            __syncthreads();
        }
        __syncthreads();
        bitonic_desc(keys, KCAP);
    }
}

// IoU > 0.45 test, exact on the boundary band
__device__ __forceinline__ bool iou_gt(const float4& a, float aa, const float4& d, float dd){
    float ix1 = fmaxf(a.x, d.x), iy1 = fmaxf(a.y, d.y);
    float ix2 = fminf(a.z, d.z), iy2 = fminf(a.w, d.w);
    float iw = fmaxf(__fsub_rn(ix2, ix1), 0.0f);
    float ih = fmaxf(__fsub_rn(iy2, iy1), 0.0f);
    float inter = __fmul_rn(iw, ih);
    if (inter <= 0.0f) return false;
    float uni = __fsub_rn(__fadd_rn(aa, dd), inter);
    if (uni <= 0.0f) return false;
    if (inter > 0.46f*uni) return true;
    if (inter < 0.44f*uni) return false;
    return __fdiv_rn(inter, uni) > 0.45f;
}

// ---------------- K2: fused per-(b,c) candidate sort + greedy NMS + det push --------
#define SMEMA_BYTES 20864   // max(keys 8K + keys2 4K + h2 2K = 14336, smat 20800)
__global__ void __launch_bounds__(BDIM, 3) k_class(const float* __restrict__ x){
    __shared__ __align__(16) unsigned char smemA[SMEMA_BYTES];
    __shared__ float4 sbox[TK1];
    __shared__ float  sarea[TK1];
    __shared__ float  sS[TK1];
    __shared__ unsigned skept[NW32];
    __shared__ unsigned wtot2[16];
    __shared__ unsigned s_t32;
    __shared__ int s_ok2, s_cnt2;
    unsigned long long* keys  = (unsigned long long*)smemA;            // 1024
    unsigned long long* keys2 = (unsigned long long*)(smemA + 8192);   // 512
    unsigned*           h2    = (unsigned*)(smemA + 8192 + 4096);      // 512 bins
    unsigned*           smat  = (unsigned*)smemA;   // overwrites all after consumption

    int bc = blockIdx.x, b = bc / NC, c = bc % NC;
    int tid = threadIdx.x, bd = blockDim.x, wid = tid >> 5, lane = tid & 31;

    if (tid == 0){ s_ok2 = 0; s_cnt2 = 0; }
    const unsigned long long* sorted;

    int cnt = g_candCnt[bc*CNT_STRIDE];
    if (cnt >= TK1 && cnt <= CCAP){
        // happy path: exact top-400 inside candidate list; prune to <=512 then sort
        const unsigned long long* src = &g_cand[(size_t)bc*CCAP];
        for (int i = tid; i < CCAP; i += bd) keys[i] = (i < cnt) ? src[i] : 0ULL;
        for (int i = tid; i < 512;  i += bd){ h2[i] = 0u; keys2[i] = 0ULL; }
        __syncthreads();
        const unsigned K0 = f2u(T0F), K1v = f2u(1.0f);
        for (int i = tid; i < cnt; i += bd)
            atomicAdd(&h2[cls_bin((unsigned)(keys[i] >> 32), K0, K1v)], 1u);
        __syncthreads();
        // suffix over 512 bins (1 bin per thread, bd == 512)
        unsigned sown = h2[tid];
        unsigned ssuf = sown;
        #pragma unroll
        for (int o = 1; o < 32; o <<= 1){
            unsigned xv = __shfl_down_sync(0xFFFFFFFFu, ssuf, o);
            if (lane + o < 32) ssuf += xv;
        }
        if (lane == 0) wtot2[wid] = ssuf;
        __syncthreads();
        unsigned wab = 0;
        for (int w = wid + 1; w < 16; w++) wab += wtot2[w];
        unsigned St = ssuf + wab, above = St - sown;
        if ((int)St >= TK1 && (int)above < TK1 && St <= 512u){
            // crossing bin B* = tid; invert with ceil => exact set equivalence
            s_t32 = (tid == 0) ? 0u
                : K0 + (unsigned)((((unsigned long long)tid * (K1v - K0)) + 511ULL) >> 9);
            s_ok2 = 1;
        }
        __syncthreads();
        if (s_ok2){
            unsigned t32 = s_t32;
            for (int base = 0; base < CCAP; base += bd){
                int i = base + tid;
                unsigned long long v = keys[i];
                bool pred = ((unsigned)(v >> 32)) >= t32 && v != 0ULL;
                unsigned ball = __ballot_sync(0xFFFFFFFFu, pred);
                int n = __popc(ball);
                int wbase = 0;
                if (lane == 0 && n) wbase = atomicAdd(&s_cnt2, n);
                wbase = __shfl_sync(0xFFFFFFFFu, wbase, 0);
                if (pred){
                    int off = __popc(ball & ((1u << lane) - 1u));
                    if (wbase + off < 512) keys2[wbase + off] = v;
                }
            }
            __syncthreads();
            bitonic_desc(keys2, 512);
            sorted = keys2;
        } else {
            bitonic_desc(keys, CCAP);
            sorted = keys;
        }
    } else {
        topk_fallback_x(x, b, c, TK1, keys);   // exact, rare
        sorted = keys;
    }

    for (int r = tid; r < TK1; r += bd){
        unsigned long long kk = sorted[r];
        int idx  = (int)(~(unsigned)(kk & 0xFFFFFFFFu));
        float sc = u2f((unsigned)(kk >> 32));
        float4 bx = g_boxes[(size_t)b*PRI + idx];
        sbox[r] = bx; sS[r] = sc;
        sarea[r] = __fmul_rn(__fsub_rn(bx.z,bx.x), __fsub_rn(bx.w,bx.y));
        g_selIdx[bc*TK1 + r] = idx;
    }
    __syncthreads();   // keys fully consumed; smat may overwrite

    // transposed, task-balanced suppression bitmatrix over 16 warps.
    for (int t = wid; t < 91; t += 16){
        int wdx = 0, rem = t;
        while (rem >= NW32 - wdx){ rem -= NW32 - wdx; wdx++; }
        int ichunk = wdx + rem;
        int jb = wdx << 5, ib = ichunk << 5;
        int jj = jb + lane;
        int jjc = min(jj, TK1 - 1);
        float4 jb4 = sbox[jjc]; float ja = sarea[jjc];
        int imax = min(32, TK1 - ib);
        for (int ii = 0; ii < imax; ii++){
            int i = ib + ii;
            float4 a = sbox[i]; float aa = sarea[i];   // broadcast
            bool gt = (jj < i) && iou_gt(a, aa, jb4, ja);
            unsigned m = __ballot_sync(0xFFFFFFFFu, gt);
            if (lane == ii) smat[i*NW32 + wdx] = m;
        }
    }
    __syncthreads();

    // sequential greedy scan; scan-warp varies per block to spread across SMSPs
    int swid = blockIdx.x & 15;
    if (wid == swid){
        unsigned kept32 = 0;
        unsigned row = (lane < NW32) ? smat[lane] : 0u;
        float sc = sS[0];
        for (int i = 0; i < TK1; i++){
            unsigned nrow = 0u; float nsc = 0.f;
            if (i + 1 < TK1){
                if (lane < NW32) nrow = smat[(i+1)*NW32 + lane];
                nsc = sS[i+1];
            }
            bool any = __any_sync(0xFFFFFFFFu, (row & kept32) != 0u);
            if (sc > 0.01f && !any && lane == (i >> 5)) kept32 |= 1u << (i & 31);
            row = nrow; sc = nsc;
        }
        if (lane < NW32) skept[lane] = kept32;
    }
    __syncthreads();

    // push kept dets (unordered) + histogram increment.
    const unsigned K0 = f2u(T0F), K1v = f2u(1.0f);
    for (int base = 0; base < TK1; base += bd){
        int r = base + tid;
        bool inb = (r < TK1);
        bool kp = false; float sc = -1.0f;
        if (inb){
            kp = (skept[r >> 5] >> (r & 31)) & 1u;
            sc = sS[r];
        }
        unsigned ball = __ballot_sync(0xFFFFFFFFu, kp);
        int n = __popc(ball);
        int wbase = 0;
        if (lane == 0 && n) wbase = atomicAdd(&g_detCnt[b*CNT_STRIDE], n);
        wbase = __shfl_sync(0xFFFFFFFFu, wbase, 0);
        if (kp){
            int off = __popc(ball & ((1u << lane) - 1u));
            unsigned flat = (unsigned)(c*TK1 + r);
            unsigned k32 = f2u(sc);
            g_detCompact[(size_t)b*NDET + wbase + off] =
                ((unsigned long long)k32 << 32) | (~flat);
            atomicAdd(&g_detHist[b*NHB + det_bin(k32, K0, K1v)], 1u);
        }
    }
}

// ---------------- K3a: 64-block det threshold + slice compaction ----------------
__global__ void __launch_bounds__(512) k_det_compact(){
    __shared__ unsigned long long s_TB;
    __shared__ int s_ok;
    __shared__ unsigned wtot[16];
    int blk = blockIdx.x;
    int b = blk >> 3, s = blk & (NSLC-1);
    int tid = threadIdx.x, bd = blockDim.x;
    int wid = tid >> 5, lane = tid & 31;

    int N = min(g_detCnt[b*CNT_STRIDE], NDET);
    int s0 = (N * s) / NSLC;
    int s1 = (N * (s + 1)) / NSLC;
    const unsigned long long* g = &g_detCompact[(size_t)b*NDET];

    if (tid == 0) s_ok = 0;
    __syncthreads();

    unsigned long long Tb = 0ULL;
    bool useTb = false;
    if (N > KCAP){
        const unsigned K0 = f2u(T0F), K1v = f2u(1.0f);
        int b0 = tid*2;
        unsigned h0 = g_detHist[b*NHB + b0];
        unsigned h1 = g_detHist[b*NHB + b0 + 1];
        unsigned sown = h0 + h1;
        unsigned ssuf = sown;
        #pragma unroll
        for (int o = 1; o < 32; o <<= 1){
            unsigned xv = __shfl_down_sync(0xFFFFFFFFu, ssuf, o);
            if (lane + o < 32) ssuf += xv;
        }
        if (lane == 0) wtot[wid] = ssuf;
        __syncthreads();
        unsigned wab = 0;
        for (int w = wid + 1; w < 16; w++) wab += wtot[w];
        unsigned St = ssuf + wab;
        unsigned above = St - sown;
        int crossBin = -1; unsigned crossSuffix = 0;
        unsigned run = above;
        if ((int)run < TK2 && (int)(run + h1) >= TK2){ crossBin = b0 + 1; crossSuffix = run + h1; }
        run += h1;
        if (crossBin < 0 && (int)run < TK2 && (int)(run + h0) >= TK2){ crossBin = b0; crossSuffix = run + h0; }
        if (crossBin >= 0 && crossSuffix <= KCAP){
            unsigned tb32 = (crossBin == 0) ? 0u
                : K0 + (unsigned)((((unsigned long long)crossBin * (K1v - K0)) + 1023ULL) >> 10);
            s_TB = (crossBin == 0) ? 0ULL : ((unsigned long long)tb32 << 32);
            s_ok = 1;
        }
        __syncthreads();
        if (s_ok){ Tb = s_TB; useTb = true; }
        else {
            if (tid == 0 && s == 0) g_detFlag[b] = 1;
            return;
        }
    }
    __syncthreads();

    int len = s1 - s0;
    for (int base = 0; base < len; base += bd){
        int i = base + tid;
        bool inb = (i < len);
        unsigned long long v = inb ? g[s0 + i] : 0ULL;
        bool pred = inb && (!useTb || v >= Tb);
        unsigned ball = __ballot_sync(0xFFFFFFFFu, pred);
        int n = __popc(ball);
        int wbase = 0;
        if (lane == 0 && n) wbase = atomicAdd(&g_detTopCnt[b*CNT_STRIDE], n);
        wbase = __shfl_sync(0xFFFFFFFFu, wbase, 0);
        if (pred){
            int off = __popc(ball & ((1u << lane) - 1u));
            if (wbase + off < KCAP) g_detTop[b*KCAP + wbase + off] = v;
        }
    }
}

// ---------------- K3b: per-batch sort of <=512 keys + rasterize ----------------
__global__ void __launch_bounds__(1024) k_det_raster(float* __restrict__ out){
    __shared__ unsigned hist[4096];
    __shared__ __align__(16) unsigned long long keys[KCAP];
    __shared__ unsigned long long wmn[32], wmx[32];
    __shared__ unsigned long long s_lo, s_hi, s_T;
    __shared__ int s_above, s_done, s_cnt;
    __shared__ unsigned wtot[32];
    __shared__ float sS2[TK2];
    __shared__ int   sCh[TK2];
    __shared__ int4  sCo[TK2];
    __shared__ unsigned char sV[TK2];
    int b = blockIdx.x, tid = threadIdx.x, bd = blockDim.x;
    int wid = tid >> 5, lane = tid & 31;

    if (tid == 0){ s_cnt = 0; s_done = 0; s_above = 0; }
    __syncthreads();

    if (!g_detFlag[b]){
        int cnt = min(g_detTopCnt[b*CNT_STRIDE], KCAP);
        for (int i = tid; i < KCAP; i += bd)
            keys[i] = (i < cnt) ? g_detTop[b*KCAP + i] : 0ULL;
        __syncthreads();
        bitonic_desc(keys, KCAP);
    } else {
        const unsigned long long* g = &g_detCompact[(size_t)b*NDET];
        int N = min(g_detCnt[b*CNT_STRIDE], NDET);
        for (int i = tid; i < KCAP; i += bd) keys[i] = 0ULL;
        __syncthreads();
        unsigned long long mn = 0xFFFFFFFFFFFFFFFFULL, mx = 0ULL;
        for (int i = tid; i < N; i += bd){
            unsigned long long v = g[i];
            if (v < mn) mn = v;
            if (v > mx) mx = v;
        }
        #pragma unroll
        for (int o = 16; o; o >>= 1){
            unsigned long long a = __shfl_down_sync(0xFFFFFFFFu, mn, o);
            unsigned long long z = __shfl_down_sync(0xFFFFFFFFu, mx, o);
            if (a < mn) mn = a;
            if (z > mx) mx = z;
        }
        if (lane == 0){ wmn[wid] = mn; wmx[wid] = mx; }
        __syncthreads();
        if (tid == 0){
            unsigned long long m1 = wmn[0], m2 = wmx[0];
            for (int w = 1; w < 32; w++){
                if (wmn[w] < m1) m1 = wmn[w];
                if (wmx[w] > m2) m2 = wmx[w];
            }
            s_lo = m1; s_hi = m2;
        }
        __syncthreads();
        for (int pass = 0; pass < 10 && !s_done; pass++){
            unsigned long long lo = s_lo, hi = s_hi;
            int above = s_above;
            unsigned long long range = hi - lo;
            int bits = 64 - __clzll(range | 1ULL);
            int shift = (bits > 12) ? (bits - 12) : 0;
            int nb = (int)((range >> shift) + 1ULL);
            for (int i = tid; i < nb; i += bd) hist[i] = 0u;
            __syncthreads();
            for (int i = tid; i < N; i += bd){
                unsigned long long v = g[i];
                if (v >= lo && v <= hi)
                    atomicAdd(&hist[(unsigned)((v - lo) >> shift)], 1u);
            }
            __syncthreads();
            int b0 = tid * 4;
            int bhi2 = min(b0 + 4, nb);
            unsigned sown = 0;
            for (int bb = b0; bb < bhi2; bb++) sown += hist[bb];
            unsigned ssuf2 = sown;
            #pragma unroll
            for (int o = 1; o < 32; o <<= 1){
                unsigned xv = __shfl_down_sync(0xFFFFFFFFu, ssuf2, o);
                if (lane + o < 32) ssuf2 += xv;
            }
            if (lane == 0) wtot[wid] = ssuf2;
            __syncthreads();
            unsigned wab2 = 0;
            for (int w = wid + 1; w < 32; w++) wab2 += wtot[w];
            unsigned St2 = ssuf2 + wab2;
            unsigned aboveT = St2 - sown;
            __syncthreads();
            if (b0 < nb && (int)(above + St2) >= TK2 && (int)(above + aboveT) < TK2){
                int running = above + (int)aboveT;
                for (int bb = bhi2 - 1; bb >= b0; bb--){
                    int cb = (int)hist[bb];
                    if (running < TK2 && running + cb >= TK2){
                        unsigned long long Tc = lo + ((unsigned long long)bb << shift);
                        if (running + cb <= KCAP){ s_T = Tc; s_done = 1; }
                        else {
                            s_lo = Tc;
                            unsigned long long nhix = lo + (((unsigned long long)bb + 1ULL) << shift) - 1ULL;
                            s_hi = (nhix < hi) ? nhix : hi;
                            s_above = running;
                        }
                        break;
                    }
                    running += cb;
                }
            }
            __syncthreads();
        }
        unsigned long long Tb = s_done ? s_T : s_lo;
        for (int base = 0; base < N; base += bd){
            int i = base + tid;
            bool pred = (i < N) && (g[i] >= Tb);
            unsigned long long v = pred ? g[i] : 0ULL;
            unsigned ball = __ballot_sync(0xFFFFFFFFu, pred);
            int n = __popc(ball);
            int wbase = 0;
            if (lane == 0 && n) wbase = atomicAdd(&s_cnt, n);
            wbase = __shfl_sync(0xFFFFFFFFu, wbase, 0);
            if (pred){
                int off = __popc(ball & ((1u << lane) - 1u));
                if (wbase + off < KCAP) keys[wbase + off] = v;
            }
        }
        __syncthreads();
        bitonic_desc(keys, KCAP);
    }

    for (int k = tid; k < TK2; k += bd){
        unsigned long long kk = keys[k];
        int fi   = (int)(~(unsigned)(kk & 0xFFFFFFFFu));
        float s  = u2f((unsigned)(kk >> 32));
        int c = fi / TK1, r = fi % TK1;
        bool valid = (kk != 0ULL) && (s >= 0.6f);
        int idx = valid ? g_selIdx[(b*NC + c)*TK1 + r] : 0;
        float4 bx = g_boxes[(size_t)b*PRI + idx];
        int4 co;
        co.x = (int)rintf(__fmul_rn(bx.x, (float)OGRID));
        co.y = (int)rintf(__fmul_rn(bx.y, (float)OGRID));
        co.z = (int)rintf(__fmul_rn(bx.z, (float)OGRID));
        co.w = (int)rintf(__fmul_rn(bx.w, (float)OGRID));
        sS2[k] = s; sCh[k] = valid ? c : 0; sCo[k] = co; sV[k] = valid ? 1 : 0;
    }
    __syncthreads();

    for (int cell = tid; cell < OGRID*OGRID; cell += bd){
        int y = cell / OGRID, xp = cell % OGRID;
        float* o = out + ((size_t)b*OGRID*OGRID + cell) * 81;
        for (int ch = 0; ch < 81; ch++) o[ch] = 0.0f;
        for (int k = 0; k < TK2; k++){
            if (sV[k]){
                int4 co = sCo[k];
                if (y >= co.y && y < co.w && xp >= co.x && xp < co.z)
                    o[sCh[k]] = sS2[k];     // ascending k: last writer == max k
            }
        }
    }
}

// ---------------- launch ----------------
extern "C" void kernel_launch(void* const* d_in, const int* in_sizes, int n_in,
                              void* d_out, int out_size){
    const float* x = (const float*)d_in[0];
    float* out = (float*)d_out;
    k_zero<<<1, 1024>>>();
    k_nop<<<1, 32>>>();    // shifts ncu capture slot onto k_class
    dim3 g1((PRI + TPRI - 1) / TPRI, BATCH);
    k_decode<<<g1, 128>>>(x);
    k_class<<<BATCH*NC, BDIM>>>(x);
    k_det_compact<<<BATCH*NSLC, 512>>>();
    k_det_raster<<<BATCH, 1024>>>(out);
}